// round 13
// baseline (speedup 1.0000x reference)
#include <cuda_runtime.h>
#include <cuda_fp16.h>
#include <cstdint>

#define NA 100000
#define NB 100000
#define NE 1600000
#define BF 128
#define AF 128

// ---------------------------------------------------------------------------
// Device scratch (allocation-free rule: device globals)
// ---------------------------------------------------------------------------
__device__ __half g_support[(size_t)NB * AF];  // 25.6 MB  a_support (fp16)
__device__ uint4  g_wpack4[8 * 16 * 32];       // W frags, q-paired (64 KB)
__device__ int    g_count[NA];                 // per-row counts / fill cursor
__device__ int    g_excl[NA];                  // block-local exclusive scan
__device__ int    g_start[NA + 1];             // CSR row starts
__device__ int    g_bsum[256];                 // per-scan-block sums
__device__ int2   g_edge[NE];                  // CSR-ordered {col, val bits}

#define SCAN_BS 512
#define SCAN_NBLK ((NA + SCAN_BS - 1) / SCAN_BS)   // 196

__device__ __forceinline__ unsigned int h2_bits(__half2 h) {
    return *reinterpret_cast<unsigned int*>(&h);
}
__device__ __forceinline__ unsigned int f2tf32(float f) {
    unsigned int r;
    asm("cvt.rna.tf32.f32 %0, %1;" : "=r"(r) : "f"(f));
    return r;
}
__device__ __forceinline__ void mma_tf32(float acc[4], uint4 a,
                                         unsigned int b0, unsigned int b1) {
    asm("mma.sync.aligned.m16n8k8.row.col.f32.tf32.tf32.f32 "
        "{%0,%1,%2,%3}, {%4,%5,%6,%7}, {%8,%9}, {%0,%1,%2,%3};"
        : "+f"(acc[0]), "+f"(acc[1]), "+f"(acc[2]), "+f"(acc[3])
        : "r"(a.x), "r"(a.y), "r"(a.z), "r"(a.w), "r"(b0), "r"(b1));
}

// ---------------------------------------------------------------------------
// Kernel 0: pack W into q-PAIRED mma b-fragment order.
// g_wpack4[p][j][lane] = {b0(q=2p), b1(2p), b0(2p+1), b1(2p+1)}
//   b0(q) = tf32(W[q*8 + lane%4][j*8 + lane/4]), b1(q) = ... +4 row.
// ---------------------------------------------------------------------------
__global__ __launch_bounds__(256) void pack_w_kernel(const float* __restrict__ W) {
    int idx = blockIdx.x * blockDim.x + threadIdx.x;
    if (idx >= 8 * 16 * 32) return;
    int lane = idx & 31;
    int j    = (idx >> 5) & 15;
    int p    = idx >> 9;
    int t = lane & 3;
    int n = j * 8 + (lane >> 2);
    int q0 = 2 * p, q1 = 2 * p + 1;
    uint4 v;
    v.x = f2tf32(W[(size_t)(q0 * 8 + t) * AF + n]);
    v.y = f2tf32(W[(size_t)(q0 * 8 + t + 4) * AF + n]);
    v.z = f2tf32(W[(size_t)(q1 * 8 + t) * AF + n]);
    v.w = f2tf32(W[(size_t)(q1 * 8 + t + 4) * AF + n]);
    g_wpack4[idx] = v;
}

// ---------------------------------------------------------------------------
// Kernel 1: tensor-core GEMM  g_support = fp16(B @ W), tf32 mma.sync.
// A staged per 16-k phase into FRAGMENT-ORDERED smem (double-buffered):
//   As u4-index = ((qq*4 + wr)*2 + h)*32 + t*8 + g, regs = mma a-frag order.
// Compute: 4 LDS.128 (a-frags) + 8 LDG.128 (W pairs) + 16 mma per phase.
// ---------------------------------------------------------------------------
__global__ __launch_bounds__(256, 2) void gemm_kernel(const float* __restrict__ B) {
    __shared__ unsigned int As[2][2048];   // 2 x 8 KB (512 uint4 each)

    const int tid  = threadIdx.x;
    const int warp = tid >> 5;
    const int lane = tid & 31;
    const int g    = lane >> 2;
    const int t    = lane & 3;
    const int wr   = warp >> 1;
    const int wc   = warp & 1;
    const int row0 = blockIdx.x * 128;
    const int JB   = wc * 8;

    float acc[2][8][4];
    #pragma unroll
    for (int rt = 0; rt < 2; rt++)
        #pragma unroll
        for (int j = 0; j < 8; j++)
            #pragma unroll
            for (int c = 0; c < 4; c++) acc[rt][j][c] = 0.0f;

    // Staging slots: row = tid>>2 (+64), c4 = tid&3 (16B of k per row)
    const int s_r0  = tid >> 2;
    const int s_r1  = s_r0 + 64;
    const int s_c4  = tid & 3;
    const int s_gr0 = min(row0 + s_r0, NB - 1);
    const int s_gr1 = min(row0 + s_r1, NB - 1);
    // Per-slot fragment coords (g,m same for both rows; wr differs by 2)
    const int s_qq  = s_c4 >> 1;
    const int s_hi  = s_c4 & 1;
    const int s_g   = s_r0 & 7;          // == s_r1 & 7
    const int s_m   = (s_r0 >> 3) & 3;   // == (s_r1 >> 3) & 3
    const int s_h   = s_m >> 1;
    const int s_reg = s_hi * 2 + (s_m & 1);
    const int s_wr0 = s_r0 >> 5;
    const int s_wr1 = s_r1 >> 5;
    const int s_b0  = ((s_qq * 4 + s_wr0) * 2 + s_h) * 32;   // uint4 base
    const int s_b1  = ((s_qq * 4 + s_wr1) * 2 + s_h) * 32;

    auto stage = [&](int buf, int kb) {
        float4 v0 = *(const float4*)(B + (size_t)s_gr0 * BF + kb + s_c4 * 4);
        float4 v1 = *(const float4*)(B + (size_t)s_gr1 * BF + kb + s_c4 * 4);
        unsigned int* S = As[buf];
        S[(s_b0 + 0 * 8 + s_g) * 4 + s_reg] = f2tf32(v0.x);
        S[(s_b0 + 1 * 8 + s_g) * 4 + s_reg] = f2tf32(v0.y);
        S[(s_b0 + 2 * 8 + s_g) * 4 + s_reg] = f2tf32(v0.z);
        S[(s_b0 + 3 * 8 + s_g) * 4 + s_reg] = f2tf32(v0.w);
        S[(s_b1 + 0 * 8 + s_g) * 4 + s_reg] = f2tf32(v1.x);
        S[(s_b1 + 1 * 8 + s_g) * 4 + s_reg] = f2tf32(v1.y);
        S[(s_b1 + 2 * 8 + s_g) * 4 + s_reg] = f2tf32(v1.z);
        S[(s_b1 + 3 * 8 + s_g) * 4 + s_reg] = f2tf32(v1.w);
    };

    const int a_lane = t * 8 + g;        // compute-side uint4 lane index

    stage(0, 0);
    __syncthreads();

    for (int ph = 0; ph < 8; ph++) {
        const int buf = ph & 1;
        if (ph < 7) stage(buf ^ 1, (ph + 1) * 16);   // prefetch next phase

        // ---- A fragments: 4 x LDS.128 (qq x half)
        const unsigned int* S = As[buf];
        uint4 aq0h0 = *(const uint4*)&S[(((0 * 4 + wr) * 2 + 0) * 32 + a_lane) * 4];
        uint4 aq0h1 = *(const uint4*)&S[(((0 * 4 + wr) * 2 + 1) * 32 + a_lane) * 4];
        uint4 aq1h0 = *(const uint4*)&S[(((1 * 4 + wr) * 2 + 0) * 32 + a_lane) * 4];
        uint4 aq1h1 = *(const uint4*)&S[(((1 * 4 + wr) * 2 + 1) * 32 + a_lane) * 4];

        // ---- W pairs + mma, in two j-halves to bound registers
        #pragma unroll
        for (int jh = 0; jh < 2; jh++) {
            uint4 w4[4];
            #pragma unroll
            for (int j2 = 0; j2 < 4; j2++)
                w4[j2] = __ldg(&g_wpack4[(ph * 16 + JB + jh * 4 + j2) * 32 + lane]);
            #pragma unroll
            for (int j2 = 0; j2 < 4; j2++) {
                int j = jh * 4 + j2;
                mma_tf32(acc[0][j], aq0h0, w4[j2].x, w4[j2].y);
                mma_tf32(acc[1][j], aq0h1, w4[j2].x, w4[j2].y);
                mma_tf32(acc[0][j], aq1h0, w4[j2].z, w4[j2].w);
                mma_tf32(acc[1][j], aq1h1, w4[j2].z, w4[j2].w);
            }
        }
        __syncthreads();
    }

    // ---- Epilogue: fp16 store
    const int R0 = row0 + wr * 32;
    #pragma unroll
    for (int rt = 0; rt < 2; rt++) {
        int r_lo = R0 + rt * 16 + g;
        int r_hi = r_lo + 8;
        #pragma unroll
        for (int j = 0; j < 8; j++) {
            int n = (JB + j) * 8 + t * 2;
            if (r_lo < NB) {
                __half2 h = __floats2half2_rn(acc[rt][j][0], acc[rt][j][1]);
                *(unsigned int*)(g_support + (size_t)r_lo * AF + n) = h2_bits(h);
            }
            if (r_hi < NB) {
                __half2 h = __floats2half2_rn(acc[rt][j][2], acc[rt][j][3]);
                *(unsigned int*)(g_support + (size_t)r_hi * AF + n) = h2_bits(h);
            }
        }
    }
}

// ---------------------------------------------------------------------------
// CSR build chain (side stream, concurrent with GEMM). g_count drains back
// to 0 via place_kernel's atomicSub -> replay-safe.
// ---------------------------------------------------------------------------
__global__ __launch_bounds__(256) void hist_kernel(const int* __restrict__ rows) {
    int e = blockIdx.x * blockDim.x + threadIdx.x;
    if (e < NE) atomicAdd(&g_count[rows[e]], 1);
}

__global__ __launch_bounds__(SCAN_BS) void scan1_kernel() {
    __shared__ int wsum[16];
    const int t    = threadIdx.x;
    const int lane = t & 31;
    const int wid  = t >> 5;
    const int idx  = blockIdx.x * SCAN_BS + t;
    int x = (idx < NA) ? g_count[idx] : 0;

    int v = x;
    #pragma unroll
    for (int off = 1; off < 32; off <<= 1) {
        int y = __shfl_up_sync(0xffffffffu, v, off);
        if (lane >= off) v += y;
    }
    if (lane == 31) wsum[wid] = v;
    __syncthreads();
    if (t < 16) {
        int s = wsum[t];
        #pragma unroll
        for (int off = 1; off < 16; off <<= 1) {
            int y = __shfl_up_sync(0x0000ffffu, s, off);
            if (t >= off) s += y;
        }
        wsum[t] = s;
    }
    __syncthreads();
    int incl = v + (wid ? wsum[wid - 1] : 0);
    if (idx < NA) g_excl[idx] = incl - x;
    if (t == SCAN_BS - 1) g_bsum[blockIdx.x] = incl;
}

__global__ __launch_bounds__(SCAN_BS) void scan3_kernel() {
    __shared__ int ws[16];
    const int b    = blockIdx.x;
    const int t    = threadIdx.x;
    const int lane = t & 31;
    const int wid  = t >> 5;

    int v = (t < b) ? g_bsum[t] : 0;       // b <= 195 < 512
    #pragma unroll
    for (int off = 16; off > 0; off >>= 1)
        v += __shfl_down_sync(0xffffffffu, v, off);
    if (lane == 0) ws[wid] = v;
    __syncthreads();
    if (t < 16) {
        int s = ws[t];
        #pragma unroll
        for (int off = 8; off > 0; off >>= 1)
            s += __shfl_down_sync(0x0000ffffu, s, off);
        if (t == 0) ws[0] = s;
    }
    __syncthreads();
    const int base = ws[0];
    const int i = b * SCAN_BS + t;
    if (i < NA) g_start[i] = g_excl[i] + base;
    if (i == 0) g_start[NA] = NE;
}

__global__ __launch_bounds__(256) void place_kernel(const int*   __restrict__ rows,
                                                    const int*   __restrict__ cols,
                                                    const float* __restrict__ vals) {
    int e = blockIdx.x * blockDim.x + threadIdx.x;
    if (e >= NE) return;
    int row = rows[e];
    int old = atomicSub(&g_count[row], 1);       // drains count back to 0
    int pos = g_start[row] + old - 1;
    int2 p;
    p.x = cols[e];
    p.y = __float_as_int(vals[e]);
    g_edge[pos] = p;
}

// ---------------------------------------------------------------------------
// SpMM + bias: one warp per output row. fp16 gather (8B/lane), fp32 math,
// single fp32 STG per out row.
// ---------------------------------------------------------------------------
__global__ __launch_bounds__(256) void spmm_kernel(const float* __restrict__ bias,
                                                   float*       __restrict__ out) {
    const int warp = (blockIdx.x * blockDim.x + threadIdx.x) >> 5;
    const int lane = threadIdx.x & 31;
    if (warp >= NA) return;

    const int s    = g_start[warp];
    const int eend = g_start[warp + 1];

    float4 acc = ((const float4*)bias)[lane];

    int e = s;
    for (; e + 4 <= eend; e += 4) {
        int2 e0 = g_edge[e],     e1 = g_edge[e + 1];
        int2 e2 = g_edge[e + 2], e3 = g_edge[e + 3];
        float v0 = __int_as_float(e0.y), v1 = __int_as_float(e1.y);
        float v2 = __int_as_float(e2.y), v3 = __int_as_float(e3.y);
        uint2 p0 = __ldg((const uint2*)(g_support + (size_t)e0.x * AF) + lane);
        uint2 p1 = __ldg((const uint2*)(g_support + (size_t)e1.x * AF) + lane);
        uint2 p2 = __ldg((const uint2*)(g_support + (size_t)e2.x * AF) + lane);
        uint2 p3 = __ldg((const uint2*)(g_support + (size_t)e3.x * AF) + lane);
        {
            float2 a = __half22float2(*reinterpret_cast<__half2*>(&p0.x));
            float2 b = __half22float2(*reinterpret_cast<__half2*>(&p0.y));
            acc.x += v0 * a.x; acc.y += v0 * a.y; acc.z += v0 * b.x; acc.w += v0 * b.y;
        }
        {
            float2 a = __half22float2(*reinterpret_cast<__half2*>(&p1.x));
            float2 b = __half22float2(*reinterpret_cast<__half2*>(&p1.y));
            acc.x += v1 * a.x; acc.y += v1 * a.y; acc.z += v1 * b.x; acc.w += v1 * b.y;
        }
        {
            float2 a = __half22float2(*reinterpret_cast<__half2*>(&p2.x));
            float2 b = __half22float2(*reinterpret_cast<__half2*>(&p2.y));
            acc.x += v2 * a.x; acc.y += v2 * a.y; acc.z += v2 * b.x; acc.w += v2 * b.y;
        }
        {
            float2 a = __half22float2(*reinterpret_cast<__half2*>(&p3.x));
            float2 b = __half22float2(*reinterpret_cast<__half2*>(&p3.y));
            acc.x += v3 * a.x; acc.y += v3 * a.y; acc.z += v3 * b.x; acc.w += v3 * b.y;
        }
    }
    for (; e < eend; e++) {
        int2 ed = g_edge[e];
        float v = __int_as_float(ed.y);
        uint2 p = __ldg((const uint2*)(g_support + (size_t)ed.x * AF) + lane);
        float2 a = __half22float2(*reinterpret_cast<__half2*>(&p.x));
        float2 b = __half22float2(*reinterpret_cast<__half2*>(&p.y));
        acc.x += v * a.x; acc.y += v * a.y; acc.z += v * b.x; acc.w += v * b.y;
    }

    ((float4*)(out + (size_t)warp * AF))[lane] = acc;
}

// ---------------------------------------------------------------------------
// Launch: forked-capture parallel branches.
//   main stream : pack -> gemm ----------------+--> spmm
//   side stream : hist -> scan1 -> scan3 -> place
// ---------------------------------------------------------------------------
extern "C" void kernel_launch(void* const* d_in, const int* in_sizes, int n_in,
                              void* d_out, int out_size) {
    const float* b_input   = (const float*)d_in[0];
    const int*   edge_rows = (const int*)  d_in[1];
    const int*   edge_cols = (const int*)  d_in[2];
    const float* edge_vals = (const float*)d_in[3];
    const float* a_weight  = (const float*)d_in[4];
    const float* a_bias    = (const float*)d_in[5];
    float*       out       = (float*)d_out;

    cudaStream_t s2;
    cudaStreamCreateWithFlags(&s2, cudaStreamNonBlocking);
    cudaEvent_t ev_fork, ev_join;
    cudaEventCreateWithFlags(&ev_fork, cudaEventDisableTiming);
    cudaEventCreateWithFlags(&ev_join, cudaEventDisableTiming);

    // ---- fork
    cudaEventRecord(ev_fork, 0);
    cudaStreamWaitEvent(s2, ev_fork, 0);

    // ---- main branch: W pack + GEMM
    pack_w_kernel<<<(8 * 16 * 32 + 255) / 256, 256>>>(a_weight);
    gemm_kernel<<<(NB + 127) / 128, 256>>>(b_input);

    // ---- side branch: CSR build
    hist_kernel<<<(NE + 255) / 256, 256, 0, s2>>>(edge_rows);
    scan1_kernel<<<SCAN_NBLK, SCAN_BS, 0, s2>>>();
    scan3_kernel<<<SCAN_NBLK, SCAN_BS, 0, s2>>>();
    place_kernel<<<(NE + 255) / 256, 256, 0, s2>>>(edge_rows, edge_cols, edge_vals);
    cudaEventRecord(ev_join, s2);

    // ---- join, then SpMM (needs g_support + g_edge/g_start)
    cudaStreamWaitEvent(0, ev_join, 0);
    spmm_kernel<<<(NA * 32 + 255) / 256, 256>>>(a_bias, out);
}

// round 14
// speedup vs baseline: 1.1130x; 1.1130x over previous
#include <cuda_runtime.h>
#include <cuda_fp16.h>
#include <cstdint>

#define NA 100000
#define NB 100000
#define NE 1600000
#define BF 128
#define AF 128

// ---------------------------------------------------------------------------
// Device scratch (allocation-free rule: device globals)
// ---------------------------------------------------------------------------
__device__ __half g_support[(size_t)NB * AF];  // 25.6 MB  a_support (fp16)
__device__ uint2  g_wpackh[8 * 16 * 32];       // W fp16 b-frags (32 KB)
__device__ int    g_count[NA];                 // per-row counts / fill cursor
__device__ int    g_excl[NA];                  // block-local exclusive scan
__device__ int    g_start[NA + 1];             // CSR row starts
__device__ int    g_bsum[256];                 // per-scan-block sums
__device__ int2   g_edge[NE];                  // CSR-ordered {col, val bits}

#define SCAN_BS 512
#define SCAN_NBLK ((NA + SCAN_BS - 1) / SCAN_BS)   // 196

__device__ __forceinline__ unsigned int h2_bits(__half2 h) {
    return *reinterpret_cast<unsigned int*>(&h);
}
// D += A(16x16 f16) x B(16x8 f16), f32 accum
__device__ __forceinline__ void mma_f16(float acc[4],
                                        unsigned int a0, unsigned int a1,
                                        unsigned int a2, unsigned int a3,
                                        unsigned int b0, unsigned int b1) {
    asm("mma.sync.aligned.m16n8k16.row.col.f32.f16.f16.f32 "
        "{%0,%1,%2,%3}, {%4,%5,%6,%7}, {%8,%9}, {%0,%1,%2,%3};"
        : "+f"(acc[0]), "+f"(acc[1]), "+f"(acc[2]), "+f"(acc[3])
        : "r"(a0), "r"(a1), "r"(a2), "r"(a3), "r"(b0), "r"(b1));
}

// ---------------------------------------------------------------------------
// Kernel 0: pack W[128,128] fp32 -> fp16 mma b-fragment order.
// g_wpackh[q][j][lane] (q: k-chunk of 16, j: n-tile of 8, lane: (g=lane/4,
// t=lane%4)):
//   .x = {W[q*16+2t][n], W[q*16+2t+1][n]}   (half2, n = j*8+g)
//   .y = {W[q*16+2t+8][n], W[q*16+2t+9][n]}
// ---------------------------------------------------------------------------
__global__ __launch_bounds__(256) void pack_w_kernel(const float* __restrict__ W) {
    int idx = blockIdx.x * blockDim.x + threadIdx.x;
    if (idx >= 8 * 16 * 32) return;
    int lane = idx & 31;
    int j    = (idx >> 5) & 15;
    int q    = idx >> 9;
    int t = lane & 3;
    int n = j * 8 + (lane >> 2);
    int k0 = q * 16 + 2 * t;
    uint2 v;
    v.x = h2_bits(__floats2half2_rn(W[(size_t)k0 * AF + n],
                                    W[(size_t)(k0 + 1) * AF + n]));
    v.y = h2_bits(__floats2half2_rn(W[(size_t)(k0 + 8) * AF + n],
                                    W[(size_t)(k0 + 9) * AF + n]));
    g_wpackh[idx] = v;
}

// ---------------------------------------------------------------------------
// Kernel 1: tensor-core GEMM  g_support = fp16(B @ W), fp16 mma m16n8k16.
// 256 threads = 8 warps; block tile 128x128; warp = 32 rows x 64 cols.
// A staged per 16-k phase as fp16 rows (4 KB/buffer, double-buffered):
//   As[row][k] halves; staging stores are byte-contiguous (addr = tid*8).
// Compute per phase: 8 LDS.32 (conflict-free) + 8 LDG.64 (W) + 16 mma.
// ---------------------------------------------------------------------------
__global__ __launch_bounds__(256, 2) void gemm_kernel(const float* __restrict__ B) {
    __shared__ __half As[2][128 * 16];   // 2 x 4 KB

    const int tid  = threadIdx.x;
    const int warp = tid >> 5;
    const int lane = tid & 31;
    const int g    = lane >> 2;
    const int t    = lane & 3;
    const int wr   = warp >> 1;
    const int wc   = warp & 1;
    const int row0 = blockIdx.x * 128;
    const int JB   = wc * 8;
    const int ra   = wr * 32 + g;        // warp-local a-frag base row

    float acc[2][8][4];
    #pragma unroll
    for (int rt = 0; rt < 2; rt++)
        #pragma unroll
        for (int j = 0; j < 8; j++)
            #pragma unroll
            for (int c = 0; c < 4; c++) acc[rt][j][c] = 0.0f;

    // Staging: thread -> (row = tid>>2, quarter = tid&3) and (+64 rows).
    // STS addr = tid*8 bytes (slot0) — fully contiguous.
    const int s_r0  = tid >> 2;
    const int s_c4  = tid & 3;
    const int s_gr0 = min(row0 + s_r0, NB - 1);
    const int s_gr1 = min(row0 + s_r0 + 64, NB - 1);

    auto stage = [&](int buf, int kb) {
        float4 v0 = *(const float4*)(B + (size_t)s_gr0 * BF + kb + s_c4 * 4);
        float4 v1 = *(const float4*)(B + (size_t)s_gr1 * BF + kb + s_c4 * 4);
        uint2 p0, p1;
        p0.x = h2_bits(__floats2half2_rn(v0.x, v0.y));
        p0.y = h2_bits(__floats2half2_rn(v0.z, v0.w));
        p1.x = h2_bits(__floats2half2_rn(v1.x, v1.y));
        p1.y = h2_bits(__floats2half2_rn(v1.z, v1.w));
        *(uint2*)&As[buf][(size_t)s_r0 * 16 + s_c4 * 4]        = p0;
        *(uint2*)&As[buf][(size_t)(s_r0 + 64) * 16 + s_c4 * 4] = p1;
    };

    stage(0, 0);
    __syncthreads();

    for (int ph = 0; ph < 8; ph++) {     // one 16-k chunk per phase
        const int buf = ph & 1;
        if (ph < 7) stage(buf ^ 1, (ph + 1) * 16);   // prefetch next phase

        const __half* S = As[buf];
        // a-frags: rows ra(+8)(+16)(+24), k = 2t(+8). 8x LDS.32, conflict-free.
        unsigned int a00 = *(const unsigned int*)&S[(ra     ) * 16 + 2 * t];
        unsigned int a01 = *(const unsigned int*)&S[(ra +  8) * 16 + 2 * t];
        unsigned int a02 = *(const unsigned int*)&S[(ra     ) * 16 + 2 * t + 8];
        unsigned int a03 = *(const unsigned int*)&S[(ra +  8) * 16 + 2 * t + 8];
        unsigned int a10 = *(const unsigned int*)&S[(ra + 16) * 16 + 2 * t];
        unsigned int a11 = *(const unsigned int*)&S[(ra + 24) * 16 + 2 * t];
        unsigned int a12 = *(const unsigned int*)&S[(ra + 16) * 16 + 2 * t + 8];
        unsigned int a13 = *(const unsigned int*)&S[(ra + 24) * 16 + 2 * t + 8];

        #pragma unroll
        for (int j = 0; j < 8; j++) {
            uint2 w = __ldg(&g_wpackh[(ph * 16 + JB + j) * 32 + lane]);
            mma_f16(acc[0][j], a00, a01, a02, a03, w.x, w.y);
            mma_f16(acc[1][j], a10, a11, a12, a13, w.x, w.y);
        }
        __syncthreads();
    }

    // ---- Epilogue: fp16 store (c-layout: c0,c1 row r cols 2t,2t+1; c2,c3 r+8)
    const int R0 = row0 + wr * 32;
    #pragma unroll
    for (int rt = 0; rt < 2; rt++) {
        int r_lo = R0 + rt * 16 + g;
        int r_hi = r_lo + 8;
        #pragma unroll
        for (int j = 0; j < 8; j++) {
            int n = (JB + j) * 8 + t * 2;
            if (r_lo < NB) {
                __half2 h = __floats2half2_rn(acc[rt][j][0], acc[rt][j][1]);
                *(unsigned int*)(g_support + (size_t)r_lo * AF + n) = h2_bits(h);
            }
            if (r_hi < NB) {
                __half2 h = __floats2half2_rn(acc[rt][j][2], acc[rt][j][3]);
                *(unsigned int*)(g_support + (size_t)r_hi * AF + n) = h2_bits(h);
            }
        }
    }
}

// ---------------------------------------------------------------------------
// CSR build chain (side stream, concurrent with GEMM). g_count drains back
// to 0 via place_kernel's atomicSub -> replay-safe.
// ---------------------------------------------------------------------------
__global__ __launch_bounds__(256) void hist_kernel(const int* __restrict__ rows) {
    int e = blockIdx.x * blockDim.x + threadIdx.x;
    if (e < NE) atomicAdd(&g_count[rows[e]], 1);
}

__global__ __launch_bounds__(SCAN_BS) void scan1_kernel() {
    __shared__ int wsum[16];
    const int t    = threadIdx.x;
    const int lane = t & 31;
    const int wid  = t >> 5;
    const int idx  = blockIdx.x * SCAN_BS + t;
    int x = (idx < NA) ? g_count[idx] : 0;

    int v = x;
    #pragma unroll
    for (int off = 1; off < 32; off <<= 1) {
        int y = __shfl_up_sync(0xffffffffu, v, off);
        if (lane >= off) v += y;
    }
    if (lane == 31) wsum[wid] = v;
    __syncthreads();
    if (t < 16) {
        int s = wsum[t];
        #pragma unroll
        for (int off = 1; off < 16; off <<= 1) {
            int y = __shfl_up_sync(0x0000ffffu, s, off);
            if (t >= off) s += y;
        }
        wsum[t] = s;
    }
    __syncthreads();
    int incl = v + (wid ? wsum[wid - 1] : 0);
    if (idx < NA) g_excl[idx] = incl - x;
    if (t == SCAN_BS - 1) g_bsum[blockIdx.x] = incl;
}

__global__ __launch_bounds__(SCAN_BS) void scan3_kernel() {
    __shared__ int ws[16];
    const int b    = blockIdx.x;
    const int t    = threadIdx.x;
    const int lane = t & 31;
    const int wid  = t >> 5;

    int v = (t < b) ? g_bsum[t] : 0;       // b <= 195 < 512
    #pragma unroll
    for (int off = 16; off > 0; off >>= 1)
        v += __shfl_down_sync(0xffffffffu, v, off);
    if (lane == 0) ws[wid] = v;
    __syncthreads();
    if (t < 16) {
        int s = ws[t];
        #pragma unroll
        for (int off = 8; off > 0; off >>= 1)
            s += __shfl_down_sync(0x0000ffffu, s, off);
        if (t == 0) ws[0] = s;
    }
    __syncthreads();
    const int base = ws[0];
    const int i = b * SCAN_BS + t;
    if (i < NA) g_start[i] = g_excl[i] + base;
    if (i == 0) g_start[NA] = NE;
}

__global__ __launch_bounds__(256) void place_kernel(const int*   __restrict__ rows,
                                                    const int*   __restrict__ cols,
                                                    const float* __restrict__ vals) {
    int e = blockIdx.x * blockDim.x + threadIdx.x;
    if (e >= NE) return;
    int row = rows[e];
    int old = atomicSub(&g_count[row], 1);       // drains count back to 0
    int pos = g_start[row] + old - 1;
    int2 p;
    p.x = cols[e];
    p.y = __float_as_int(vals[e]);
    g_edge[pos] = p;
}

// ---------------------------------------------------------------------------
// SpMM + bias: one warp per output row. fp16 gather (8B/lane), fp32 math,
// single fp32 STG per out row.
// ---------------------------------------------------------------------------
__global__ __launch_bounds__(256) void spmm_kernel(const float* __restrict__ bias,
                                                   float*       __restrict__ out) {
    const int warp = (blockIdx.x * blockDim.x + threadIdx.x) >> 5;
    const int lane = threadIdx.x & 31;
    if (warp >= NA) return;

    const int s    = g_start[warp];
    const int eend = g_start[warp + 1];

    float4 acc = ((const float4*)bias)[lane];

    int e = s;
    for (; e + 4 <= eend; e += 4) {
        int2 e0 = g_edge[e],     e1 = g_edge[e + 1];
        int2 e2 = g_edge[e + 2], e3 = g_edge[e + 3];
        float v0 = __int_as_float(e0.y), v1 = __int_as_float(e1.y);
        float v2 = __int_as_float(e2.y), v3 = __int_as_float(e3.y);
        uint2 p0 = __ldg((const uint2*)(g_support + (size_t)e0.x * AF) + lane);
        uint2 p1 = __ldg((const uint2*)(g_support + (size_t)e1.x * AF) + lane);
        uint2 p2 = __ldg((const uint2*)(g_support + (size_t)e2.x * AF) + lane);
        uint2 p3 = __ldg((const uint2*)(g_support + (size_t)e3.x * AF) + lane);
        {
            float2 a = __half22float2(*reinterpret_cast<__half2*>(&p0.x));
            float2 b = __half22float2(*reinterpret_cast<__half2*>(&p0.y));
            acc.x += v0 * a.x; acc.y += v0 * a.y; acc.z += v0 * b.x; acc.w += v0 * b.y;
        }
        {
            float2 a = __half22float2(*reinterpret_cast<__half2*>(&p1.x));
            float2 b = __half22float2(*reinterpret_cast<__half2*>(&p1.y));
            acc.x += v1 * a.x; acc.y += v1 * a.y; acc.z += v1 * b.x; acc.w += v1 * b.y;
        }
        {
            float2 a = __half22float2(*reinterpret_cast<__half2*>(&p2.x));
            float2 b = __half22float2(*reinterpret_cast<__half2*>(&p2.y));
            acc.x += v2 * a.x; acc.y += v2 * a.y; acc.z += v2 * b.x; acc.w += v2 * b.y;
        }
        {
            float2 a = __half22float2(*reinterpret_cast<__half2*>(&p3.x));
            float2 b = __half22float2(*reinterpret_cast<__half2*>(&p3.y));
            acc.x += v3 * a.x; acc.y += v3 * a.y; acc.z += v3 * b.x; acc.w += v3 * b.y;
        }
    }
    for (; e < eend; e++) {
        int2 ed = g_edge[e];
        float v = __int_as_float(ed.y);
        uint2 p = __ldg((const uint2*)(g_support + (size_t)ed.x * AF) + lane);
        float2 a = __half22float2(*reinterpret_cast<__half2*>(&p.x));
        float2 b = __half22float2(*reinterpret_cast<__half2*>(&p.y));
        acc.x += v * a.x; acc.y += v * a.y; acc.z += v * b.x; acc.w += v * b.y;
    }

    ((float4*)(out + (size_t)warp * AF))[lane] = acc;
}

// ---------------------------------------------------------------------------
// Launch: forked-capture parallel branches.
//   main stream : pack -> gemm ----------------+--> spmm
//   side stream : hist -> scan1 -> scan3 -> place
// ---------------------------------------------------------------------------
extern "C" void kernel_launch(void* const* d_in, const int* in_sizes, int n_in,
                              void* d_out, int out_size) {
    const float* b_input   = (const float*)d_in[0];
    const int*   edge_rows = (const int*)  d_in[1];
    const int*   edge_cols = (const int*)  d_in[2];
    const float* edge_vals = (const float*)d_in[3];
    const float* a_weight  = (const float*)d_in[4];
    const float* a_bias    = (const float*)d_in[5];
    float*       out       = (float*)d_out;

    cudaStream_t s2;
    cudaStreamCreateWithFlags(&s2, cudaStreamNonBlocking);
    cudaEvent_t ev_fork, ev_join;
    cudaEventCreateWithFlags(&ev_fork, cudaEventDisableTiming);
    cudaEventCreateWithFlags(&ev_join, cudaEventDisableTiming);

    // ---- fork
    cudaEventRecord(ev_fork, 0);
    cudaStreamWaitEvent(s2, ev_fork, 0);

    // ---- main branch: W pack + GEMM
    pack_w_kernel<<<(8 * 16 * 32 + 255) / 256, 256>>>(a_weight);
    gemm_kernel<<<(NB + 127) / 128, 256>>>(b_input);

    // ---- side branch: CSR build
    hist_kernel<<<(NE + 255) / 256, 256, 0, s2>>>(edge_rows);
    scan1_kernel<<<SCAN_NBLK, SCAN_BS, 0, s2>>>();
    scan3_kernel<<<SCAN_NBLK, SCAN_BS, 0, s2>>>();
    place_kernel<<<(NE + 255) / 256, 256, 0, s2>>>(edge_rows, edge_cols, edge_vals);
    cudaEventRecord(ev_join, s2);

    // ---- join, then SpMM (needs g_support + g_edge/g_start)
    cudaStreamWaitEvent(0, ev_join, 0);
    spmm_kernel<<<(NA * 32 + 255) / 256, 256>>>(a_bias, out);
}